// round 5
// baseline (speedup 1.0000x reference)
#include <cuda_runtime.h>
#include <cstdint>
#include <math.h>

#define Nb 512
#define Tt 64
#define Dd 512
#define Hh 512
#define FH 2048

// Persistent state (device globals: no allocations allowed)
__device__ float g_h[2][Nb * Hh];
__device__ float g_c[2][Nb * Hh];
__device__ float g_attn[Nb * Hh];

// ---------------------------------------------------------------------------
// init: h0 = c0 = mean over the 16 spatial positions of A
// ---------------------------------------------------------------------------
__global__ __launch_bounds__(128) void init_kernel(const float* __restrict__ A) {
    int n = blockIdx.x, tid = threadIdx.x;
    const float4* base = (const float4*)(A + (size_t)n * Hh * 16);
#pragma unroll
    for (int i = 0; i < 4; i++) {
        int r = tid + i * 128;
        float4 v0 = base[r * 4 + 0], v1 = base[r * 4 + 1];
        float4 v2 = base[r * 4 + 2], v3 = base[r * 4 + 3];
        float s = (v0.x + v0.y + v0.z + v0.w) + (v1.x + v1.y + v1.z + v1.w)
                + (v2.x + v2.y + v2.z + v2.w) + (v3.x + v3.y + v3.z + v3.w);
        float m = s * (1.0f / 16.0f);
        g_h[0][n * Hh + r] = m;
        g_c[0][n * Hh + r] = m;
    }
}

// ---------------------------------------------------------------------------
// attention: scores = (h . A)/sqrt(H), softmax over 16, attn = A @ w
// one block per batch row; A row kept in registers (read exactly once)
// ---------------------------------------------------------------------------
__global__ __launch_bounds__(128) void attn_kernel(const float* __restrict__ A, int pi) {
    int n = blockIdx.x, tid = threadIdx.x;
    int lane = tid & 31, warp = tid >> 5;
    const float* hbuf = g_h[pi] + (size_t)n * Hh;
    const float4* base = (const float4*)(A + (size_t)n * Hh * 16);

    float Av[4][16];
    float hv[4];
    float part[16];
#pragma unroll
    for (int p = 0; p < 16; p++) part[p] = 0.f;

#pragma unroll
    for (int i = 0; i < 4; i++) {
        int r = tid + i * 128;
#pragma unroll
        for (int q = 0; q < 4; q++) {
            float4 v = base[r * 4 + q];
            Av[i][q * 4 + 0] = v.x; Av[i][q * 4 + 1] = v.y;
            Av[i][q * 4 + 2] = v.z; Av[i][q * 4 + 3] = v.w;
        }
        hv[i] = hbuf[r];
#pragma unroll
        for (int p = 0; p < 16; p++) part[p] += hv[i] * Av[i][p];
    }

#pragma unroll
    for (int off = 16; off >= 1; off >>= 1)
#pragma unroll
        for (int p = 0; p < 16; p++)
            part[p] += __shfl_xor_sync(0xffffffffu, part[p], off);

    __shared__ float red[4][16];
    __shared__ float w[16];
    if (lane == 0) {
#pragma unroll
        for (int p = 0; p < 16; p++) red[warp][p] = part[p];
    }
    __syncthreads();
    if (tid == 0) {
        const float scale = 0.044194173824159216f;  // 1/sqrt(512)
        float sc[16];
        float mx = -1e30f;
#pragma unroll
        for (int p = 0; p < 16; p++) {
            sc[p] = (red[0][p] + red[1][p] + red[2][p] + red[3][p]) * scale;
            mx = fmaxf(mx, sc[p]);
        }
        float s = 0.f;
#pragma unroll
        for (int p = 0; p < 16; p++) { float e = expf(sc[p] - mx); w[p] = e; s += e; }
        float inv = 1.f / s;
#pragma unroll
        for (int p = 0; p < 16; p++) w[p] *= inv;
    }
    __syncthreads();

    float wl[16];
#pragma unroll
    for (int p = 0; p < 16; p++) wl[p] = w[p];
    float* ao = g_attn + (size_t)n * Hh;
#pragma unroll
    for (int i = 0; i < 4; i++) {
        float s = 0.f;
#pragma unroll
        for (int p = 0; p < 16; p++) s += Av[i][p] * wl[p];
        ao[tid + i * 128] = s;
    }
}

// ---------------------------------------------------------------------------
// fused step GEMM + gates.
// a = [x_t | h | attn] @ [Wx; Wh; Wattn] + b,  tf32 mma, K = 1536.
// Block tile: 64 rows x 32 h'-cols (gathered as 4 gate strips of 32 -> 128 a-cols)
// Grid (16, 8) = 128 CTAs. cp.async 3-stage pipeline, 1 bar/iter.
// Epilogue applies LSTM gates; h/c double-buffered.
// ---------------------------------------------------------------------------
#define ASTR 20
#define BSTR 136
#define A_FLOATS (64 * ASTR)
#define STAGE_FLOATS (64 * ASTR + 16 * BSTR)  // 3456
#define NSTAGES 3
#define ITERS 96

#define CP_ASYNC16(dst, src) \
    asm volatile("cp.async.cg.shared.global [%0], [%1], 16;\n" :: "r"(dst), "l"(src))
#define CP_COMMIT() asm volatile("cp.async.commit_group;\n")
#define CP_WAIT1()  asm volatile("cp.async.wait_group 1;\n")

__device__ __forceinline__ uint32_t smem_u32(const void* p) {
    return (uint32_t)__cvta_generic_to_shared(p);
}

__global__ __launch_bounds__(256, 1) void step_kernel(
    const float* __restrict__ x, const float* __restrict__ Wx,
    const float* __restrict__ Wh, const float* __restrict__ Wattn,
    const float* __restrict__ bias, float* __restrict__ out, int t, int pi)
{
    __shared__ __align__(16) float sm[NSTAGES * STAGE_FLOATS];
    const int tid = threadIdx.x;
    const int j0 = blockIdx.x * 32;
    const int n0 = blockIdx.y * 64;
    const float* h_in = g_h[pi];
    const float* c_in = g_c[pi];
    float* h_out = g_h[pi ^ 1];
    float* c_out = g_c[pi ^ 1];

    const float* xbase = x + (size_t)n0 * Tt * Dd + (size_t)t * Dd;
    const int am = tid >> 2, akq = (tid & 3) * 4;

    const int lane = tid & 31, wid = tid >> 5;
    const int wm = wid & 1, wn = wid >> 1;
    const int gid = lane >> 2, tg = lane & 3;

    float acc[2][4][4];
#pragma unroll
    for (int fm = 0; fm < 2; fm++)
#pragma unroll
        for (int fn = 0; fn < 4; fn++)
#pragma unroll
            for (int e = 0; e < 4; e++) acc[fm][fn][e] = 0.f;

    auto issue = [&](int i) {
        float* stg = sm + (i % NSTAGES) * STAGE_FLOATS;
        int seg = i >> 5;
        int kl = (i & 31) << 4;
        const float* Ab; size_t astr; const float* W;
        if (seg == 0)      { Ab = xbase;                        astr = (size_t)Tt * Dd; W = Wx; }
        else if (seg == 1) { Ab = h_in   + (size_t)n0 * Hh;     astr = Hh;              W = Wh; }
        else               { Ab = g_attn + (size_t)n0 * Hh;     astr = Hh;              W = Wattn; }
        // A tile: 64 x 16 (one 16B chunk per thread)
        const float* asrc = Ab + (size_t)am * astr + kl + akq;
        CP_ASYNC16(smem_u32(stg + am * ASTR + akq), asrc);
        // B tile: 16 x 128 gathered gate columns (two 16B chunks per thread)
        float* Bst = stg + A_FLOATS;
#pragma unroll
        for (int j = 0; j < 2; j++) {
            int e = tid + j * 256;
            int k = e >> 5, n4 = e & 31;
            const float* bsrc = W + (size_t)(kl + k) * FH + (n4 >> 3) * 512 + j0 + (n4 & 7) * 4;
            CP_ASYNC16(smem_u32(Bst + k * BSTR + n4 * 4), bsrc);
        }
    };

    issue(0); CP_COMMIT();
    issue(1); CP_COMMIT();

    for (int i = 0; i < ITERS; i++) {
        CP_WAIT1();
        __syncthreads();
        const float* As = sm + (i % NSTAGES) * STAGE_FLOATS;
        const float* Bs = As + A_FLOATS;
#pragma unroll
        for (int k8 = 0; k8 < 2; k8++) {
            int kb = k8 * 8;
            uint32_t a[2][4], bf[4][2];
#pragma unroll
            for (int fm = 0; fm < 2; fm++) {
                int row = wm * 32 + fm * 16 + gid;
                a[fm][0] = __float_as_uint(As[row * ASTR + kb + tg]);
                a[fm][1] = __float_as_uint(As[(row + 8) * ASTR + kb + tg]);
                a[fm][2] = __float_as_uint(As[row * ASTR + kb + tg + 4]);
                a[fm][3] = __float_as_uint(As[(row + 8) * ASTR + kb + tg + 4]);
            }
#pragma unroll
            for (int fn = 0; fn < 4; fn++) {
                int col = wn * 32 + fn * 8 + gid;
                bf[fn][0] = __float_as_uint(Bs[(kb + tg) * BSTR + col]);
                bf[fn][1] = __float_as_uint(Bs[(kb + tg + 4) * BSTR + col]);
            }
#pragma unroll
            for (int fm = 0; fm < 2; fm++)
#pragma unroll
                for (int fn = 0; fn < 4; fn++) {
                    asm volatile(
                        "mma.sync.aligned.m16n8k8.row.col.f32.tf32.tf32.f32 "
                        "{%0,%1,%2,%3}, {%4,%5,%6,%7}, {%8,%9}, {%0,%1,%2,%3};\n"
                        : "+f"(acc[fm][fn][0]), "+f"(acc[fm][fn][1]),
                          "+f"(acc[fm][fn][2]), "+f"(acc[fm][fn][3])
                        : "r"(a[fm][0]), "r"(a[fm][1]), "r"(a[fm][2]), "r"(a[fm][3]),
                          "r"(bf[fn][0]), "r"(bf[fn][1]));
                }
        }
        if (i + 2 < ITERS) issue(i + 2);
        CP_COMMIT();
    }

    __syncthreads();
    // stash a-tile (64 x 128) in smem for gate gathering
    float (*atile)[132] = (float(*)[132])sm;
#pragma unroll
    for (int fm = 0; fm < 2; fm++)
#pragma unroll
        for (int fn = 0; fn < 4; fn++) {
            int R = wm * 32 + fm * 16 + gid, C = wn * 32 + fn * 8 + tg * 2;
            atile[R][C]         = acc[fm][fn][0];
            atile[R][C + 1]     = acc[fm][fn][1];
            atile[R + 8][C]     = acc[fm][fn][2];
            atile[R + 8][C + 1] = acc[fm][fn][3];
        }
    __syncthreads();

    int col = tid & 31;
    int r0 = tid >> 5;
    float bi = bias[j0 + col];
    float bff = bias[512 + j0 + col];
    float bo = bias[1024 + j0 + col];
    float bg = bias[1536 + j0 + col];
#pragma unroll
    for (int q = 0; q < 8; q++) {
        int row = r0 + q * 8;
        float vi = atile[row][col]      + bi;
        float vf = atile[row][col + 32] + bff;
        float vo = atile[row][col + 64] + bo;
        float vg = atile[row][col + 96] + bg;
        float ig = 1.f / (1.f + expf(-vi));
        float fg = 1.f / (1.f + expf(-vf));
        float og = 1.f / (1.f + expf(-vo));
        float gg = tanhf(vg);
        int n = n0 + row, hc = j0 + col;
        float cold = c_in[n * Hh + hc];
        float cn = fg * cold + ig * gg;
        float hn = og * tanhf(cn);
        c_out[n * Hh + hc] = cn;
        h_out[n * Hh + hc] = hn;
        out[((size_t)n * Tt + t) * Hh + hc] = hn;
    }
}

// ---------------------------------------------------------------------------
extern "C" void kernel_launch(void* const* d_in, const int* in_sizes, int n_in,
                              void* d_out, int out_size) {
    const float* x     = (const float*)d_in[0];
    const float* A     = (const float*)d_in[1];
    const float* Wx    = (const float*)d_in[2];
    const float* Wh    = (const float*)d_in[3];
    const float* Wattn = (const float*)d_in[4];
    const float* b     = (const float*)d_in[5];
    float* out = (float*)d_out;

    init_kernel<<<Nb, 128>>>(A);
    for (int t = 0; t < Tt; t++) {
        int pi = t & 1;
        attn_kernel<<<Nb, 128>>>(A, pi);
        step_kernel<<<dim3(16, 8), 256>>>(x, Wx, Wh, Wattn, b, out, t, pi);
    }
}